// round 14
// baseline (speedup 1.0000x reference)
#include <cuda_runtime.h>
#include <cuda_fp16.h>

#define NMAX 100000
#define EMAX 1600000
#define CMAX 128

// Scratch (__device__ globals: allocation-free rule)
__device__ __half d_G[(size_t)NMAX * CMAX];       // messages (half)
__device__ __half d_B1[(size_t)NMAX * CMAX];      // activations (half)
__device__ __half d_B2[(size_t)NMAX * CMAX];
__device__ float  d_dinv[NMAX];
__device__ int    d_cnt[NMAX];
__device__ int    d_cur[NMAX];
__device__ int    d_off[NMAX + 1];
__device__ int    d_csr[EMAX];
__device__ unsigned long long d_flags[128];       // decoupled-lookback flags
__device__ unsigned d_runctr;                     // epoch (increments per run)
__device__ unsigned d_gmin[64];
__device__ int    d_done;

__device__ __forceinline__ unsigned enc_f(float f) {
    unsigned u = __float_as_uint(f);
    return (u & 0x80000000u) ? ~u : (u | 0x80000000u);
}
__device__ __forceinline__ float dec_f(unsigned e) {
    unsigned u = (e & 0x80000000u) ? (e ^ 0x80000000u) : ~e;
    return __uint_as_float(u);
}

// 4 halves (8B) from fp32 or half source row
__device__ __forceinline__ uint2 loadH4(const float* A, size_t row, int k4) {
    float4 v = __ldg((const float4*)(A + row * 128) + k4);
    __half2 h0 = __floats2half2_rn(v.x, v.y);
    __half2 h1 = __floats2half2_rn(v.z, v.w);
    uint2 r;
    r.x = *(unsigned*)&h0;
    r.y = *(unsigned*)&h1;
    return r;
}
__device__ __forceinline__ uint2 loadH4(const __half* A, size_t row, int k4) {
    return __ldg((const uint2*)(A + row * 128) + k4);
}

// ================= degree histogram (vectorized) + epoch bump =================
__global__ void k_hist(const int* __restrict__ dst, int E) {
    if (blockIdx.x == 0 && threadIdx.x == 0) atomicAdd(&d_runctr, 1u);
    int i = blockIdx.x * blockDim.x + threadIdx.x;
    int E4 = E >> 2;
    if (i < E4) {
        int4 v = __ldg((const int4*)dst + i);
        atomicAdd(&d_cnt[v.x], 1);
        atomicAdd(&d_cnt[v.y], 1);
        atomicAdd(&d_cnt[v.z], 1);
        atomicAdd(&d_cnt[v.w], 1);
    }
    int t = E4 * 4 + i;                     // tail (E % 4 elements)
    if (i < (E & 3)) atomicAdd(&d_cnt[dst[t]], 1);
}

// ================= single-pass CSR scan (decoupled lookback) ====================
// 1024 elements/block (4/thread). Flags are epoch-tagged 64-bit words:
//   [63:32]=epoch  [31:30]=state(1=AGG,2=PREFIX)  [29:0]=value
// so no flag-reset launch is needed across graph replays.
// Also does scan3's duties: dinv, cnt/cur cleanup, d_off[N], gmin/done init.
__global__ void k_scanAll(int N, int E) {
    __shared__ int sh[256];
    __shared__ int sExcl;
    int t = threadIdx.x;
    int bid = blockIdx.x;
    int base = bid * 1024 + t * 4;
    int c0 = 0, c1 = 0, c2 = 0, c3 = 0;
    if (base + 3 < N) {
        int4 v = *(const int4*)&d_cnt[base];
        c0 = v.x; c1 = v.y; c2 = v.z; c3 = v.w;
    } else {
        if (base + 0 < N) c0 = d_cnt[base + 0];
        if (base + 1 < N) c1 = d_cnt[base + 1];
        if (base + 2 < N) c2 = d_cnt[base + 2];
        if (base + 3 < N) c3 = d_cnt[base + 3];
    }
    int s = c0 + c1 + c2 + c3;
    sh[t] = s;
    __syncthreads();
    for (int d = 1; d < 256; d <<= 1) {
        int v = (t >= d) ? sh[t - d] : 0;
        __syncthreads();
        sh[t] += v;
        __syncthreads();
    }
    int total = sh[255];

    unsigned epoch = d_runctr;
    if (t < 32) {
        if (t == 0) {
            unsigned long long st = (bid == 0) ? 2ull : 1ull;  // block 0: PREFIX directly
            unsigned long long f = ((unsigned long long)epoch << 32) | (st << 30)
                                 | (unsigned long long)(unsigned)total;
            *((volatile unsigned long long*)&d_flags[bid]) = f;
        }
        int accum = 0;
        if (bid > 0) {
            int j = bid - 1;
            while (true) {
                int idx = j - t;
                unsigned st;
                int val;
                if (idx >= 0) {
                    unsigned long long f;
                    do {
                        f = *((volatile unsigned long long*)&d_flags[idx]);
                    } while ((unsigned)(f >> 32) != epoch);
                    st  = (unsigned)((f >> 30) & 3u);
                    val = (int)(f & 0x3FFFFFFFu);
                } else { st = 2u; val = 0; }
                unsigned preMask = __ballot_sync(0xFFFFFFFFu, st == 2u);
                int Lp = __ffs(preMask) - 1;        // -1 if none
                int contrib;
                if (Lp >= 0) contrib = (t <= Lp) ? val : 0;
                else         contrib = val;
#pragma unroll
                for (int o = 16; o > 0; o >>= 1)
                    contrib += __shfl_down_sync(0xFFFFFFFFu, contrib, o);
                contrib = __shfl_sync(0xFFFFFFFFu, contrib, 0);
                accum += contrib;
                if (Lp >= 0) break;
                j -= 32;
            }
        }
        if (t == 0) {
            sExcl = accum;
            if (bid > 0) {
                unsigned long long f = ((unsigned long long)epoch << 32) | (2ull << 30)
                                     | (unsigned long long)(unsigned)(accum + total);
                *((volatile unsigned long long*)&d_flags[bid]) = f;
            }
        }
    }
    __syncthreads();
    int excl = sExcl + sh[t] - s;

    if (base + 0 < N) { d_off[base + 0] = excl;                d_dinv[base + 0] = rsqrtf((float)c0 + 1.f); d_cnt[base + 0] = 0; d_cur[base + 0] = 0; }
    if (base + 1 < N) { d_off[base + 1] = excl + c0;           d_dinv[base + 1] = rsqrtf((float)c1 + 1.f); d_cnt[base + 1] = 0; d_cur[base + 1] = 0; }
    if (base + 2 < N) { d_off[base + 2] = excl + c0 + c1;      d_dinv[base + 2] = rsqrtf((float)c2 + 1.f); d_cnt[base + 2] = 0; d_cur[base + 2] = 0; }
    if (base + 3 < N) { d_off[base + 3] = excl + c0 + c1 + c2; d_dinv[base + 3] = rsqrtf((float)c3 + 1.f); d_cnt[base + 3] = 0; d_cur[base + 3] = 0; }
    if (bid == 0) {
        if (t == 0) { d_off[N] = E; d_done = 0; }
        if (t < 64) d_gmin[t] = 0xFFFFFFFFu;
    }
}

// ================= tensor-core GEMM =================
// g[row] = half(dinv[row] * (A[row] @ W)); A: [N][128] (fp32 or half), W: [128][COLS] fp32.
// 256 threads; tile = 128 rows x COLS; mma.sync.m16n8k16 (f16 in, f32 accum).
// FILL: blocks with bid < fillBlocks do the CSR fill instead.
template <int COLS, bool FILL, typename AT>
__global__ void __launch_bounds__(256)
k_gemm_mma(const AT* __restrict__ A, const float* __restrict__ W,
           __half* __restrict__ g, int N,
           const int* __restrict__ src, const int* __restrict__ dstp, int E, int fillBlocks)
{
    if (FILL && (int)blockIdx.x < fillBlocks) {
        for (int i = blockIdx.x * 256 + threadIdx.x; i < E; i += fillBlocks * 256) {
            int d = dstp[i];
            int p = atomicAdd(&d_cur[d], 1);
            d_csr[d_off[d] + p] = src[i];
        }
        return;
    }
    constexpr int AROW = 272;
    constexpr int WROW = (COLS == 128) ? 272 : 144;
    constexpr int NT = COLS / 8;

    extern __shared__ char sm[];
    char* smA = sm;
    char* smW = sm + 128 * AROW;
    const unsigned sA = (unsigned)__cvta_generic_to_shared(smA);
    const unsigned sW = (unsigned)__cvta_generic_to_shared(smW);

    const int tid = threadIdx.x;
    const int base = (blockIdx.x - (FILL ? fillBlocks : 0)) * 128;

    for (int i = tid; i < 128 * 32; i += 256) {
        int r = i >> 5, k4 = i & 31;
        int row = base + r;
        uint2 v = make_uint2(0u, 0u);
        if (row < N) v = loadH4(A, (size_t)row, k4);
        *(uint2*)(smA + r * AROW + k4 * 8) = v;
    }
    for (int i = tid; i < 128 * COLS / 4; i += 256) {
        int r = i / (COLS / 4), n4 = i % (COLS / 4);
        float4 v = __ldg((const float4*)W + i);
        __half2 h0 = __floats2half2_rn(v.x, v.y);
        __half2 h1 = __floats2half2_rn(v.z, v.w);
        uint2 u;
        u.x = *(unsigned*)&h0;
        u.y = *(unsigned*)&h1;
        *(uint2*)(smW + r * WROW + n4 * 8) = u;
    }
    __syncthreads();

    const int warp = tid >> 5;
    const int lane = tid & 31;
    const int warprow = warp * 16;
    const int lr = lane & 7;
    const int sel = lane >> 3;
    const int selLo = sel & 1;
    const int selHi = sel >> 1;

    float c[NT][4];
#pragma unroll
    for (int n = 0; n < NT; n++)
#pragma unroll
        for (int q = 0; q < 4; q++) c[n][q] = 0.f;

#pragma unroll
    for (int ks = 0; ks < 8; ks++) {
        unsigned a0, a1, a2, a3;
        unsigned aaddr = sA + (warprow + lr + selLo * 8) * AROW + ks * 32 + selHi * 16;
        asm volatile("ldmatrix.sync.aligned.m8n8.x4.shared.b16 {%0,%1,%2,%3}, [%4];"
                     : "=r"(a0), "=r"(a1), "=r"(a2), "=r"(a3) : "r"(aaddr));
#pragma unroll
        for (int p = 0; p < NT / 2; p++) {
            unsigned b0, b1, b2, b3;
            unsigned baddr = sW + (ks * 16 + lr + selLo * 8) * WROW + p * 32 + selHi * 16;
            asm volatile("ldmatrix.sync.aligned.m8n8.x4.trans.shared.b16 {%0,%1,%2,%3}, [%4];"
                         : "=r"(b0), "=r"(b1), "=r"(b2), "=r"(b3) : "r"(baddr));
            asm volatile("mma.sync.aligned.m16n8k16.row.col.f32.f16.f16.f32 "
                         "{%0,%1,%2,%3}, {%4,%5,%6,%7}, {%8,%9}, {%0,%1,%2,%3};"
                         : "+f"(c[2 * p][0]), "+f"(c[2 * p][1]), "+f"(c[2 * p][2]), "+f"(c[2 * p][3])
                         : "r"(a0), "r"(a1), "r"(a2), "r"(a3), "r"(b0), "r"(b1));
            asm volatile("mma.sync.aligned.m16n8k16.row.col.f32.f16.f16.f32 "
                         "{%0,%1,%2,%3}, {%4,%5,%6,%7}, {%8,%9}, {%0,%1,%2,%3};"
                         : "+f"(c[2 * p + 1][0]), "+f"(c[2 * p + 1][1]), "+f"(c[2 * p + 1][2]), "+f"(c[2 * p + 1][3])
                         : "r"(a0), "r"(a1), "r"(a2), "r"(a3), "r"(b2), "r"(b3));
        }
    }

    const int gq = lane >> 2;
    const int tig = lane & 3;
    int row0 = base + warprow + gq;
    int row1 = row0 + 8;
    float dv0 = (row0 < N) ? d_dinv[row0] : 0.f;
    float dv1 = (row1 < N) ? d_dinv[row1] : 0.f;
#pragma unroll
    for (int n = 0; n < NT; n++) {
        int col = n * 8 + 2 * tig;
        if (row0 < N) {
            __half2 h = __floats2half2_rn(c[n][0] * dv0, c[n][1] * dv0);
            *(__half2*)(g + (size_t)row0 * COLS + col) = h;
        }
        if (row1 < N) {
            __half2 h = __floats2half2_rn(c[n][2] * dv1, c[n][3] * dv1);
            *(__half2*)(g + (size_t)row1 * COLS + col) = h;
        }
    }
}

// ================= CSR aggregate (half msgs, fp32 accum, 1 warp/node) ============
// 8-deep software pipeline: 8 row loads in flight while the NEXT 8 indices load.
__device__ __forceinline__ void acc_u2(float& a0, float& a1, float& a2, float& a3, uint2 v) {
    float2 f0 = __half22float2(*(__half2*)&v.x);
    float2 f1 = __half22float2(*(__half2*)&v.y);
    a0 += f0.x; a1 += f0.y; a2 += f1.x; a3 += f1.y;
}

__global__ void k_agg128(const __half* __restrict__ g, const float* __restrict__ bias,
                         __half* __restrict__ out, int N)
{
    int node = (blockIdx.x * blockDim.x + threadIdx.x) >> 5;
    int lane = threadIdx.x & 31;
    if (node >= N) return;
    const uint2* gp = (const uint2*)g;

    float a0 = 0.f, a1 = 0.f, a2 = 0.f, a3 = 0.f;
    acc_u2(a0, a1, a2, a3, __ldg(&gp[(size_t)node * 32 + lane]));   // self-loop
    int s = d_off[node], e = d_off[node + 1];
    int j = s;
    int c0, c1, c2, c3, c4, c5, c6, c7;
    bool have = (j + 8 <= e);
    if (have) {
        c0 = __ldg(d_csr + j);     c1 = __ldg(d_csr + j + 1);
        c2 = __ldg(d_csr + j + 2); c3 = __ldg(d_csr + j + 3);
        c4 = __ldg(d_csr + j + 4); c5 = __ldg(d_csr + j + 5);
        c6 = __ldg(d_csr + j + 6); c7 = __ldg(d_csr + j + 7);
    }
    while (have) {
        bool nxt = (j + 16 <= e);
        int m0, m1, m2, m3, m4, m5, m6, m7;
        if (nxt) {
            m0 = __ldg(d_csr + j + 8);  m1 = __ldg(d_csr + j + 9);
            m2 = __ldg(d_csr + j + 10); m3 = __ldg(d_csr + j + 11);
            m4 = __ldg(d_csr + j + 12); m5 = __ldg(d_csr + j + 13);
            m6 = __ldg(d_csr + j + 14); m7 = __ldg(d_csr + j + 15);
        }
        uint2 v0 = __ldg(&gp[(size_t)c0 * 32 + lane]);
        uint2 v1 = __ldg(&gp[(size_t)c1 * 32 + lane]);
        uint2 v2 = __ldg(&gp[(size_t)c2 * 32 + lane]);
        uint2 v3 = __ldg(&gp[(size_t)c3 * 32 + lane]);
        uint2 v4 = __ldg(&gp[(size_t)c4 * 32 + lane]);
        uint2 v5 = __ldg(&gp[(size_t)c5 * 32 + lane]);
        uint2 v6 = __ldg(&gp[(size_t)c6 * 32 + lane]);
        uint2 v7 = __ldg(&gp[(size_t)c7 * 32 + lane]);
        acc_u2(a0, a1, a2, a3, v0); acc_u2(a0, a1, a2, a3, v1);
        acc_u2(a0, a1, a2, a3, v2); acc_u2(a0, a1, a2, a3, v3);
        acc_u2(a0, a1, a2, a3, v4); acc_u2(a0, a1, a2, a3, v5);
        acc_u2(a0, a1, a2, a3, v6); acc_u2(a0, a1, a2, a3, v7);
        c0 = m0; c1 = m1; c2 = m2; c3 = m3;
        c4 = m4; c5 = m5; c6 = m6; c7 = m7;
        j += 8;
        have = nxt;
    }
    if (j + 4 <= e) {
        int n0 = __ldg(d_csr + j),     n1 = __ldg(d_csr + j + 1);
        int n2 = __ldg(d_csr + j + 2), n3 = __ldg(d_csr + j + 3);
        uint2 v0 = __ldg(&gp[(size_t)n0 * 32 + lane]);
        uint2 v1 = __ldg(&gp[(size_t)n1 * 32 + lane]);
        uint2 v2 = __ldg(&gp[(size_t)n2 * 32 + lane]);
        uint2 v3 = __ldg(&gp[(size_t)n3 * 32 + lane]);
        acc_u2(a0, a1, a2, a3, v0); acc_u2(a0, a1, a2, a3, v1);
        acc_u2(a0, a1, a2, a3, v2); acc_u2(a0, a1, a2, a3, v3);
        j += 4;
    }
    for (; j < e; j++)
        acc_u2(a0, a1, a2, a3, __ldg(&gp[(size_t)__ldg(d_csr + j) * 32 + lane]));

    float dv = d_dinv[node];
    float4 b = __ldg((const float4*)bias + lane);
    __half2 h0 = __floats2half2_rn(fmaxf(fmaf(a0, dv, b.x), 0.f),
                                   fmaxf(fmaf(a1, dv, b.y), 0.f));
    __half2 h1 = __floats2half2_rn(fmaxf(fmaf(a2, dv, b.z), 0.f),
                                   fmaxf(fmaf(a3, dv, b.w), 0.f));
    uint2 w;
    w.x = *(unsigned*)&h0;
    w.y = *(unsigned*)&h1;
    ((uint2*)out)[(size_t)node * 32 + lane] = w;
}

// layer 3: COLS=64 -> 32 half2/row; fused min-pool + fused final (last block).
__global__ void k_agg64min(const __half* __restrict__ g, const float* __restrict__ b3,
                           float* __restrict__ out, int N)
{
    __shared__ unsigned sMin[64];
    __shared__ bool lastBlk;
    int tid = threadIdx.x;
    if (tid < 64) sMin[tid] = 0xFFFFFFFFu;
    __syncthreads();

    int node = (blockIdx.x * blockDim.x + tid) >> 5;
    int lane = tid & 31;
    if (node < N) {
        const unsigned* gp = (const unsigned*)g;
        float a0 = 0.f, a1 = 0.f;
        {
            unsigned v = __ldg(&gp[(size_t)node * 32 + lane]);
            float2 f = __half22float2(*(__half2*)&v);
            a0 += f.x; a1 += f.y;
        }
        int s = d_off[node], e = d_off[node + 1];
        int j = s;
        int c0, c1, c2, c3, c4, c5, c6, c7;
        bool have = (j + 8 <= e);
        if (have) {
            c0 = __ldg(d_csr + j);     c1 = __ldg(d_csr + j + 1);
            c2 = __ldg(d_csr + j + 2); c3 = __ldg(d_csr + j + 3);
            c4 = __ldg(d_csr + j + 4); c5 = __ldg(d_csr + j + 5);
            c6 = __ldg(d_csr + j + 6); c7 = __ldg(d_csr + j + 7);
        }
        while (have) {
            bool nxt = (j + 16 <= e);
            int m0, m1, m2, m3, m4, m5, m6, m7;
            if (nxt) {
                m0 = __ldg(d_csr + j + 8);  m1 = __ldg(d_csr + j + 9);
                m2 = __ldg(d_csr + j + 10); m3 = __ldg(d_csr + j + 11);
                m4 = __ldg(d_csr + j + 12); m5 = __ldg(d_csr + j + 13);
                m6 = __ldg(d_csr + j + 14); m7 = __ldg(d_csr + j + 15);
            }
            unsigned v0 = __ldg(&gp[(size_t)c0 * 32 + lane]);
            unsigned v1 = __ldg(&gp[(size_t)c1 * 32 + lane]);
            unsigned v2 = __ldg(&gp[(size_t)c2 * 32 + lane]);
            unsigned v3 = __ldg(&gp[(size_t)c3 * 32 + lane]);
            unsigned v4 = __ldg(&gp[(size_t)c4 * 32 + lane]);
            unsigned v5 = __ldg(&gp[(size_t)c5 * 32 + lane]);
            unsigned v6 = __ldg(&gp[(size_t)c6 * 32 + lane]);
            unsigned v7 = __ldg(&gp[(size_t)c7 * 32 + lane]);
            float2 f;
            f = __half22float2(*(__half2*)&v0); a0 += f.x; a1 += f.y;
            f = __half22float2(*(__half2*)&v1); a0 += f.x; a1 += f.y;
            f = __half22float2(*(__half2*)&v2); a0 += f.x; a1 += f.y;
            f = __half22float2(*(__half2*)&v3); a0 += f.x; a1 += f.y;
            f = __half22float2(*(__half2*)&v4); a0 += f.x; a1 += f.y;
            f = __half22float2(*(__half2*)&v5); a0 += f.x; a1 += f.y;
            f = __half22float2(*(__half2*)&v6); a0 += f.x; a1 += f.y;
            f = __half22float2(*(__half2*)&v7); a0 += f.x; a1 += f.y;
            c0 = m0; c1 = m1; c2 = m2; c3 = m3;
            c4 = m4; c5 = m5; c6 = m6; c7 = m7;
            j += 8;
            have = nxt;
        }
        if (j + 4 <= e) {
            int n0 = __ldg(d_csr + j),     n1 = __ldg(d_csr + j + 1);
            int n2 = __ldg(d_csr + j + 2), n3 = __ldg(d_csr + j + 3);
            unsigned v0 = __ldg(&gp[(size_t)n0 * 32 + lane]);
            unsigned v1 = __ldg(&gp[(size_t)n1 * 32 + lane]);
            unsigned v2 = __ldg(&gp[(size_t)n2 * 32 + lane]);
            unsigned v3 = __ldg(&gp[(size_t)n3 * 32 + lane]);
            float2 f;
            f = __half22float2(*(__half2*)&v0); a0 += f.x; a1 += f.y;
            f = __half22float2(*(__half2*)&v1); a0 += f.x; a1 += f.y;
            f = __half22float2(*(__half2*)&v2); a0 += f.x; a1 += f.y;
            f = __half22float2(*(__half2*)&v3); a0 += f.x; a1 += f.y;
            j += 4;
        }
        for (; j < e; j++) {
            unsigned v = __ldg(&gp[(size_t)__ldg(d_csr + j) * 32 + lane]);
            float2 f = __half22float2(*(__half2*)&v);
            a0 += f.x; a1 += f.y;
        }
        float dv = d_dinv[node];
        atomicMin(&sMin[2 * lane + 0], enc_f(a0 * dv));
        atomicMin(&sMin[2 * lane + 1], enc_f(a1 * dv));
    }
    __syncthreads();
    if (tid < 64) atomicMin(&d_gmin[tid], sMin[tid]);
    __threadfence();
    __syncthreads();
    if (tid == 0) {
        int old = atomicAdd(&d_done, 1);
        lastBlk = (old == (int)gridDim.x - 1);
    }
    __syncthreads();
    if (lastBlk) {
        __threadfence();
        if (tid < 64) out[tid] = dec_f(d_gmin[tid]) + __ldg(b3 + tid);
    }
}

extern "C" void kernel_launch(void* const* d_in, const int* in_sizes, int n_in,
                              void* d_out, int out_size)
{
    const float* x  = (const float*)d_in[0];
    const int*   ei = (const int*)d_in[1];
    const float* W1 = (const float*)d_in[2];
    const float* b1 = (const float*)d_in[3];
    const float* W2 = (const float*)d_in[4];
    const float* b2 = (const float*)d_in[5];
    const float* W3 = (const float*)d_in[6];
    const float* b3 = (const float*)d_in[7];
    float* out = (float*)d_out;

    int N = in_sizes[0] / 128;
    int E = in_sizes[1] / 2;
    const int* src = ei;
    const int* dst = ei + E;

    __half *B1, *B2, *G;
    cudaGetSymbolAddress((void**)&B1, d_B1);
    cudaGetSymbolAddress((void**)&B2, d_B2);
    cudaGetSymbolAddress((void**)&G, d_G);

    const int smem128 = 128 * 272 + 128 * 272;
    const int smem64  = 128 * 272 + 128 * 144;
    cudaFuncSetAttribute(k_gemm_mma<128, true,  float>,  cudaFuncAttributeMaxDynamicSharedMemorySize, smem128);
    cudaFuncSetAttribute(k_gemm_mma<128, false, __half>, cudaFuncAttributeMaxDynamicSharedMemorySize, smem128);
    cudaFuncSetAttribute(k_gemm_mma<64,  false, __half>, cudaFuncAttributeMaxDynamicSharedMemorySize, smem64);

    // CSR: hist + single-pass scan (dinv ready after scanAll; cnt/cur self-cleaned)
    k_hist<<<(E / 4 + 255) / 256, 256>>>(dst, E);
    int nblk = (N + 1023) / 1024;
    k_scanAll<<<nblk, 256>>>(N, E);

    int gb = (N + 127) / 128;
    const int fillBlocks = 512;

    // Layer 1: tensor GEMM (x @ W1 -> G) with CSR fill fused at low block ids
    k_gemm_mma<128, true, float><<<gb + fillBlocks, 256, smem128>>>(x, W1, G, N, src, dst, E, fillBlocks);
    k_agg128<<<(N * 32 + 255) / 256, 256>>>(G, b1, B2, N);

    // Layer 2
    k_gemm_mma<128, false, __half><<<gb, 256, smem128>>>(B2, W2, G, N, nullptr, nullptr, 0, 0);
    k_agg128<<<(N * 32 + 255) / 256, 256>>>(G, b2, B1, N);

    // Layer 3 (64 cols) + fused min-pool + fused final
    k_gemm_mma<64, false, __half><<<gb, 256, smem64>>>(B1, W3, G, N, nullptr, nullptr, 0, 0);
    k_agg64min<<<(N * 32 + 255) / 256, 256>>>(G, b3, out, N);
}

// round 15
// speedup vs baseline: 1.3428x; 1.3428x over previous
#include <cuda_runtime.h>
#include <cuda_fp16.h>

#define NMAX 100000
#define EMAX 1600000
#define CMAX 128

// Scratch (__device__ globals: allocation-free rule)
__device__ __half d_G[(size_t)NMAX * CMAX];       // messages (half)
__device__ __half d_B1[(size_t)NMAX * CMAX];      // activations (half)
__device__ __half d_B2[(size_t)NMAX * CMAX];
__device__ float  d_dinv[NMAX];
__device__ int    d_cnt[NMAX];
__device__ int    d_cur[NMAX];
__device__ int    d_off[NMAX + 1];
__device__ int4   d_csr4[EMAX / 4];               // CSR adjacency (int4-aligned)
__device__ int    d_blk[128];
__device__ int    d_blk2[128];
__device__ unsigned d_gmin[64];

__device__ __forceinline__ unsigned enc_f(float f) {
    unsigned u = __float_as_uint(f);
    return (u & 0x80000000u) ? ~u : (u | 0x80000000u);
}
__device__ __forceinline__ float dec_f(unsigned e) {
    unsigned u = (e & 0x80000000u) ? (e ^ 0x80000000u) : ~e;
    return __uint_as_float(u);
}

// 4 halves (8B) from fp32 or half source row
__device__ __forceinline__ uint2 loadH4(const float* A, size_t row, int k4) {
    float4 v = __ldg((const float4*)(A + row * 128) + k4);
    __half2 h0 = __floats2half2_rn(v.x, v.y);
    __half2 h1 = __floats2half2_rn(v.z, v.w);
    uint2 r;
    r.x = *(unsigned*)&h0;
    r.y = *(unsigned*)&h1;
    return r;
}
__device__ __forceinline__ uint2 loadH4(const __half* A, size_t row, int k4) {
    return __ldg((const uint2*)(A + row * 128) + k4);
}

// ================= degree histogram =================
__global__ void k_hist(const int* __restrict__ dst, int E) {
    int i = blockIdx.x * blockDim.x + threadIdx.x;
    if (i < E) atomicAdd(&d_cnt[dst[i]], 1);
}

// ================= CSR scans =================
__global__ void k_scan1(int N) {
    __shared__ int sh[256];
    int t = threadIdx.x;
    int base = blockIdx.x * 1024 + t * 4;
    int c0 = 0, c1 = 0, c2 = 0, c3 = 0;
    if (base + 3 < N) {
        int4 v = *(const int4*)&d_cnt[base];
        c0 = v.x; c1 = v.y; c2 = v.z; c3 = v.w;
    } else {
        if (base + 0 < N) c0 = d_cnt[base + 0];
        if (base + 1 < N) c1 = d_cnt[base + 1];
        if (base + 2 < N) c2 = d_cnt[base + 2];
        if (base + 3 < N) c3 = d_cnt[base + 3];
    }
    int s = c0 + c1 + c2 + c3;
    sh[t] = s;
    __syncthreads();
    for (int d = 1; d < 256; d <<= 1) {
        int v = (t >= d) ? sh[t - d] : 0;
        __syncthreads();
        sh[t] += v;
        __syncthreads();
    }
    int excl = sh[t] - s;
    if (base + 0 < N) d_off[base + 0] = excl;
    if (base + 1 < N) d_off[base + 1] = excl + c0;
    if (base + 2 < N) d_off[base + 2] = excl + c0 + c1;
    if (base + 3 < N) d_off[base + 3] = excl + c0 + c1 + c2;
    if (t == 255) d_blk[blockIdx.x] = sh[255];
}

__global__ void k_scan2(int nblk) {
    __shared__ int sh[128];
    int t = threadIdx.x;
    int v = (t < nblk) ? d_blk[t] : 0;
    sh[t] = v;
    __syncthreads();
    for (int d = 1; d < 128; d <<= 1) {
        int u = (t >= d) ? sh[t - d] : 0;
        __syncthreads();
        sh[t] += u;
        __syncthreads();
    }
    d_blk2[t] = sh[t] - v;
}

// Also: computes dinv, zeroes d_cnt/d_cur for graph replay, inits gmin.
__global__ void k_scan3(int N, int E) {
    int i = blockIdx.x * blockDim.x + threadIdx.x;
    if (i < N) {
        d_off[i] += d_blk2[i >> 10];
        d_dinv[i] = rsqrtf((float)d_cnt[i] + 1.0f);  // +1 self-loop
        d_cnt[i] = 0;                                 // self-clean for replay
        d_cur[i] = 0;
    }
    if (i == 0) d_off[N] = E;
    if (blockIdx.x == 0 && threadIdx.x < 64) d_gmin[threadIdx.x] = 0xFFFFFFFFu;
}

// ================= tensor-core GEMM =================
// g[row] = half(dinv[row] * (A[row] @ W)); A: [N][128] (fp32 or half), W: [128][COLS] fp32.
// 256 threads; tile = 128 rows x COLS; mma.sync.m16n8k16 (f16 in, f32 accum).
// FILL: blocks with bid < fillBlocks do the CSR fill instead.
template <int COLS, bool FILL, typename AT>
__global__ void __launch_bounds__(256)
k_gemm_mma(const AT* __restrict__ A, const float* __restrict__ W,
           __half* __restrict__ g, int N,
           const int* __restrict__ src, const int* __restrict__ dstp, int E, int fillBlocks)
{
    if (FILL && (int)blockIdx.x < fillBlocks) {
        int* csr = (int*)d_csr4;
        for (int i = blockIdx.x * 256 + threadIdx.x; i < E; i += fillBlocks * 256) {
            int d = dstp[i];
            int p = atomicAdd(&d_cur[d], 1);
            csr[d_off[d] + p] = src[i];
        }
        return;
    }
    constexpr int AROW = 272;
    constexpr int WROW = (COLS == 128) ? 272 : 144;
    constexpr int NT = COLS / 8;

    extern __shared__ char sm[];
    char* smA = sm;
    char* smW = sm + 128 * AROW;
    const unsigned sA = (unsigned)__cvta_generic_to_shared(smA);
    const unsigned sW = (unsigned)__cvta_generic_to_shared(smW);

    const int tid = threadIdx.x;
    const int base = (blockIdx.x - (FILL ? fillBlocks : 0)) * 128;

    for (int i = tid; i < 128 * 32; i += 256) {
        int r = i >> 5, k4 = i & 31;
        int row = base + r;
        uint2 v = make_uint2(0u, 0u);
        if (row < N) v = loadH4(A, (size_t)row, k4);
        *(uint2*)(smA + r * AROW + k4 * 8) = v;
    }
    for (int i = tid; i < 128 * COLS / 4; i += 256) {
        int r = i / (COLS / 4), n4 = i % (COLS / 4);
        float4 v = __ldg((const float4*)W + i);
        __half2 h0 = __floats2half2_rn(v.x, v.y);
        __half2 h1 = __floats2half2_rn(v.z, v.w);
        uint2 u;
        u.x = *(unsigned*)&h0;
        u.y = *(unsigned*)&h1;
        *(uint2*)(smW + r * WROW + n4 * 8) = u;
    }
    __syncthreads();

    const int warp = tid >> 5;
    const int lane = tid & 31;
    const int warprow = warp * 16;
    const int lr = lane & 7;
    const int sel = lane >> 3;
    const int selLo = sel & 1;
    const int selHi = sel >> 1;

    float c[NT][4];
#pragma unroll
    for (int n = 0; n < NT; n++)
#pragma unroll
        for (int q = 0; q < 4; q++) c[n][q] = 0.f;

#pragma unroll
    for (int ks = 0; ks < 8; ks++) {
        unsigned a0, a1, a2, a3;
        unsigned aaddr = sA + (warprow + lr + selLo * 8) * AROW + ks * 32 + selHi * 16;
        asm volatile("ldmatrix.sync.aligned.m8n8.x4.shared.b16 {%0,%1,%2,%3}, [%4];"
                     : "=r"(a0), "=r"(a1), "=r"(a2), "=r"(a3) : "r"(aaddr));
#pragma unroll
        for (int p = 0; p < NT / 2; p++) {
            unsigned b0, b1, b2, b3;
            unsigned baddr = sW + (ks * 16 + lr + selLo * 8) * WROW + p * 32 + selHi * 16;
            asm volatile("ldmatrix.sync.aligned.m8n8.x4.trans.shared.b16 {%0,%1,%2,%3}, [%4];"
                         : "=r"(b0), "=r"(b1), "=r"(b2), "=r"(b3) : "r"(baddr));
            asm volatile("mma.sync.aligned.m16n8k16.row.col.f32.f16.f16.f32 "
                         "{%0,%1,%2,%3}, {%4,%5,%6,%7}, {%8,%9}, {%0,%1,%2,%3};"
                         : "+f"(c[2 * p][0]), "+f"(c[2 * p][1]), "+f"(c[2 * p][2]), "+f"(c[2 * p][3])
                         : "r"(a0), "r"(a1), "r"(a2), "r"(a3), "r"(b0), "r"(b1));
            asm volatile("mma.sync.aligned.m16n8k16.row.col.f32.f16.f16.f32 "
                         "{%0,%1,%2,%3}, {%4,%5,%6,%7}, {%8,%9}, {%0,%1,%2,%3};"
                         : "+f"(c[2 * p + 1][0]), "+f"(c[2 * p + 1][1]), "+f"(c[2 * p + 1][2]), "+f"(c[2 * p + 1][3])
                         : "r"(a0), "r"(a1), "r"(a2), "r"(a3), "r"(b2), "r"(b3));
        }
    }

    const int gq = lane >> 2;
    const int tig = lane & 3;
    int row0 = base + warprow + gq;
    int row1 = row0 + 8;
    float dv0 = (row0 < N) ? d_dinv[row0] : 0.f;
    float dv1 = (row1 < N) ? d_dinv[row1] : 0.f;
#pragma unroll
    for (int n = 0; n < NT; n++) {
        int col = n * 8 + 2 * tig;
        if (row0 < N) {
            __half2 h = __floats2half2_rn(c[n][0] * dv0, c[n][1] * dv0);
            *(__half2*)(g + (size_t)row0 * COLS + col) = h;
        }
        if (row1 < N) {
            __half2 h = __floats2half2_rn(c[n][2] * dv1, c[n][3] * dv1);
            *(__half2*)(g + (size_t)row1 * COLS + col) = h;
        }
    }
}

// ================= CSR aggregate (half msgs, fp32 accum, 1 warp/node) ============
// Indices fetched as aligned int4 (2 LDG.128 per 8 edges) with one-batch prefetch.
__device__ __forceinline__ void acc_u2(float& a0, float& a1, float& a2, float& a3, uint2 v) {
    float2 f0 = __half22float2(*(__half2*)&v.x);
    float2 f1 = __half22float2(*(__half2*)&v.y);
    a0 += f0.x; a1 += f0.y; a2 += f1.x; a3 += f1.y;
}

__global__ void k_agg128(const __half* __restrict__ g, const float* __restrict__ bias,
                         __half* __restrict__ out, int N)
{
    int node = (blockIdx.x * blockDim.x + threadIdx.x) >> 5;
    int lane = threadIdx.x & 31;
    if (node >= N) return;
    const uint2* gp = (const uint2*)g;
    const int* csr = (const int*)d_csr4;

    float a0 = 0.f, a1 = 0.f, a2 = 0.f, a3 = 0.f;
    acc_u2(a0, a1, a2, a3, __ldg(&gp[(size_t)node * 32 + lane]));   // self-loop
    int s = d_off[node], e = d_off[node + 1];
    int j = s;
    int jal = (s + 3) & ~3;                           // 4-aligned start
    if (jal > e) jal = e;
    for (; j < jal; j++)
        acc_u2(a0, a1, a2, a3, __ldg(&gp[(size_t)__ldg(csr + j) * 32 + lane]));

    int4 ca, cb;
    bool have = (j + 8 <= e);
    if (have) {
        ca = __ldg((const int4*)(csr + j));
        cb = __ldg((const int4*)(csr + j) + 1);
    }
    while (have) {
        bool nxt = (j + 16 <= e);
        int4 ma, mb;
        if (nxt) {
            ma = __ldg((const int4*)(csr + j) + 2);
            mb = __ldg((const int4*)(csr + j) + 3);
        }
        uint2 v0 = __ldg(&gp[(size_t)ca.x * 32 + lane]);
        uint2 v1 = __ldg(&gp[(size_t)ca.y * 32 + lane]);
        uint2 v2 = __ldg(&gp[(size_t)ca.z * 32 + lane]);
        uint2 v3 = __ldg(&gp[(size_t)ca.w * 32 + lane]);
        uint2 v4 = __ldg(&gp[(size_t)cb.x * 32 + lane]);
        uint2 v5 = __ldg(&gp[(size_t)cb.y * 32 + lane]);
        uint2 v6 = __ldg(&gp[(size_t)cb.z * 32 + lane]);
        uint2 v7 = __ldg(&gp[(size_t)cb.w * 32 + lane]);
        acc_u2(a0, a1, a2, a3, v0); acc_u2(a0, a1, a2, a3, v1);
        acc_u2(a0, a1, a2, a3, v2); acc_u2(a0, a1, a2, a3, v3);
        acc_u2(a0, a1, a2, a3, v4); acc_u2(a0, a1, a2, a3, v5);
        acc_u2(a0, a1, a2, a3, v6); acc_u2(a0, a1, a2, a3, v7);
        ca = ma; cb = mb;
        j += 8;
        have = nxt;
    }
    if (j + 4 <= e) {
        int4 c = __ldg((const int4*)(csr + j));
        uint2 v0 = __ldg(&gp[(size_t)c.x * 32 + lane]);
        uint2 v1 = __ldg(&gp[(size_t)c.y * 32 + lane]);
        uint2 v2 = __ldg(&gp[(size_t)c.z * 32 + lane]);
        uint2 v3 = __ldg(&gp[(size_t)c.w * 32 + lane]);
        acc_u2(a0, a1, a2, a3, v0); acc_u2(a0, a1, a2, a3, v1);
        acc_u2(a0, a1, a2, a3, v2); acc_u2(a0, a1, a2, a3, v3);
        j += 4;
    }
    for (; j < e; j++)
        acc_u2(a0, a1, a2, a3, __ldg(&gp[(size_t)__ldg(csr + j) * 32 + lane]));

    float dv = d_dinv[node];
    float4 b = __ldg((const float4*)bias + lane);
    __half2 h0 = __floats2half2_rn(fmaxf(fmaf(a0, dv, b.x), 0.f),
                                   fmaxf(fmaf(a1, dv, b.y), 0.f));
    __half2 h1 = __floats2half2_rn(fmaxf(fmaf(a2, dv, b.z), 0.f),
                                   fmaxf(fmaf(a3, dv, b.w), 0.f));
    uint2 w;
    w.x = *(unsigned*)&h0;
    w.y = *(unsigned*)&h1;
    ((uint2*)out)[(size_t)node * 32 + lane] = w;
}

// layer 3: COLS=64 -> 32 half2/row; fused min-pool (bias deferred to k_final).
__global__ void k_agg64min(const __half* __restrict__ g, int N)
{
    __shared__ unsigned sMin[64];
    int tid = threadIdx.x;
    if (tid < 64) sMin[tid] = 0xFFFFFFFFu;
    __syncthreads();

    int node = (blockIdx.x * blockDim.x + tid) >> 5;
    int lane = tid & 31;
    if (node < N) {
        const unsigned* gp = (const unsigned*)g;
        const int* csr = (const int*)d_csr4;
        float a0 = 0.f, a1 = 0.f;
        {
            unsigned v = __ldg(&gp[(size_t)node * 32 + lane]);
            float2 f = __half22float2(*(__half2*)&v);
            a0 += f.x; a1 += f.y;
        }
        int s = d_off[node], e = d_off[node + 1];
        int j = s;
        int jal = (s + 3) & ~3;
        if (jal > e) jal = e;
        for (; j < jal; j++) {
            unsigned v = __ldg(&gp[(size_t)__ldg(csr + j) * 32 + lane]);
            float2 f = __half22float2(*(__half2*)&v);
            a0 += f.x; a1 += f.y;
        }
        int4 ca, cb;
        bool have = (j + 8 <= e);
        if (have) {
            ca = __ldg((const int4*)(csr + j));
            cb = __ldg((const int4*)(csr + j) + 1);
        }
        while (have) {
            bool nxt = (j + 16 <= e);
            int4 ma, mb;
            if (nxt) {
                ma = __ldg((const int4*)(csr + j) + 2);
                mb = __ldg((const int4*)(csr + j) + 3);
            }
            unsigned v0 = __ldg(&gp[(size_t)ca.x * 32 + lane]);
            unsigned v1 = __ldg(&gp[(size_t)ca.y * 32 + lane]);
            unsigned v2 = __ldg(&gp[(size_t)ca.z * 32 + lane]);
            unsigned v3 = __ldg(&gp[(size_t)ca.w * 32 + lane]);
            unsigned v4 = __ldg(&gp[(size_t)cb.x * 32 + lane]);
            unsigned v5 = __ldg(&gp[(size_t)cb.y * 32 + lane]);
            unsigned v6 = __ldg(&gp[(size_t)cb.z * 32 + lane]);
            unsigned v7 = __ldg(&gp[(size_t)cb.w * 32 + lane]);
            float2 f;
            f = __half22float2(*(__half2*)&v0); a0 += f.x; a1 += f.y;
            f = __half22float2(*(__half2*)&v1); a0 += f.x; a1 += f.y;
            f = __half22float2(*(__half2*)&v2); a0 += f.x; a1 += f.y;
            f = __half22float2(*(__half2*)&v3); a0 += f.x; a1 += f.y;
            f = __half22float2(*(__half2*)&v4); a0 += f.x; a1 += f.y;
            f = __half22float2(*(__half2*)&v5); a0 += f.x; a1 += f.y;
            f = __half22float2(*(__half2*)&v6); a0 += f.x; a1 += f.y;
            f = __half22float2(*(__half2*)&v7); a0 += f.x; a1 += f.y;
            ca = ma; cb = mb;
            j += 8;
            have = nxt;
        }
        if (j + 4 <= e) {
            int4 c = __ldg((const int4*)(csr + j));
            unsigned v0 = __ldg(&gp[(size_t)c.x * 32 + lane]);
            unsigned v1 = __ldg(&gp[(size_t)c.y * 32 + lane]);
            unsigned v2 = __ldg(&gp[(size_t)c.z * 32 + lane]);
            unsigned v3 = __ldg(&gp[(size_t)c.w * 32 + lane]);
            float2 f;
            f = __half22float2(*(__half2*)&v0); a0 += f.x; a1 += f.y;
            f = __half22float2(*(__half2*)&v1); a0 += f.x; a1 += f.y;
            f = __half22float2(*(__half2*)&v2); a0 += f.x; a1 += f.y;
            f = __half22float2(*(__half2*)&v3); a0 += f.x; a1 += f.y;
            j += 4;
        }
        for (; j < e; j++) {
            unsigned v = __ldg(&gp[(size_t)__ldg(csr + j) * 32 + lane]);
            float2 f = __half22float2(*(__half2*)&v);
            a0 += f.x; a1 += f.y;
        }
        float dv = d_dinv[node];
        atomicMin(&sMin[2 * lane + 0], enc_f(a0 * dv));
        atomicMin(&sMin[2 * lane + 1], enc_f(a1 * dv));
    }
    __syncthreads();
    if (tid < 64) atomicMin(&d_gmin[tid], sMin[tid]);
}

__global__ void k_final(const float* __restrict__ b3, float* __restrict__ out) {
    int c = threadIdx.x;
    out[c] = dec_f(d_gmin[c]) + b3[c];
}

extern "C" void kernel_launch(void* const* d_in, const int* in_sizes, int n_in,
                              void* d_out, int out_size)
{
    const float* x  = (const float*)d_in[0];
    const int*   ei = (const int*)d_in[1];
    const float* W1 = (const float*)d_in[2];
    const float* b1 = (const float*)d_in[3];
    const float* W2 = (const float*)d_in[4];
    const float* b2 = (const float*)d_in[5];
    const float* W3 = (const float*)d_in[6];
    const float* b3 = (const float*)d_in[7];
    float* out = (float*)d_out;

    int N = in_sizes[0] / 128;
    int E = in_sizes[1] / 2;
    const int* src = ei;
    const int* dst = ei + E;

    __half *B1, *B2, *G;
    cudaGetSymbolAddress((void**)&B1, d_B1);
    cudaGetSymbolAddress((void**)&B2, d_B2);
    cudaGetSymbolAddress((void**)&G, d_G);

    const int smem128 = 128 * 272 + 128 * 272;
    const int smem64  = 128 * 272 + 128 * 144;
    cudaFuncSetAttribute(k_gemm_mma<128, true,  float>,  cudaFuncAttributeMaxDynamicSharedMemorySize, smem128);
    cudaFuncSetAttribute(k_gemm_mma<128, false, __half>, cudaFuncAttributeMaxDynamicSharedMemorySize, smem128);
    cudaFuncSetAttribute(k_gemm_mma<64,  false, __half>, cudaFuncAttributeMaxDynamicSharedMemorySize, smem64);

    // CSR: hist + scans (dinv ready after scan3; cnt/cur self-cleaned there)
    k_hist<<<(E + 255) / 256, 256>>>(dst, E);
    int nblk = (N + 1023) / 1024;
    k_scan1<<<nblk, 256>>>(N);
    k_scan2<<<1, 128>>>(nblk);
    k_scan3<<<(N + 255) / 256, 256>>>(N, E);

    int gb = (N + 127) / 128;
    const int fillBlocks = 512;

    // Layer 1: tensor GEMM (x @ W1 -> G) with CSR fill fused at low block ids
    k_gemm_mma<128, true, float><<<gb + fillBlocks, 256, smem128>>>(x, W1, G, N, src, dst, E, fillBlocks);
    k_agg128<<<(N * 32 + 255) / 256, 256>>>(G, b1, B2, N);

    // Layer 2
    k_gemm_mma<128, false, __half><<<gb, 256, smem128>>>(B2, W2, G, N, nullptr, nullptr, 0, 0);
    k_agg128<<<(N * 32 + 255) / 256, 256>>>(G, b2, B1, N);

    // Layer 3 (64 cols) + fused min-pool
    k_gemm_mma<64, false, __half><<<gb, 256, smem64>>>(B1, W3, G, N, nullptr, nullptr, 0, 0);
    k_agg64min<<<(N * 32 + 255) / 256, 256>>>(G, N);

    k_final<<<1, 64>>>(b3, out);
}